// round 1
// baseline (speedup 1.0000x reference)
#include <cuda_runtime.h>

#define FULLM 0xffffffffu
typedef unsigned long long ull;

static __device__ __forceinline__ ull fma2(ull a, ull b, ull c){
    ull d; asm("fma.rn.f32x2 %0, %1, %2, %3;" : "=l"(d) : "l"(a), "l"(b), "l"(c)); return d;
}
static __device__ __forceinline__ ull dup2(float x){
    ull d; asm("mov.b64 %0, {%1, %1};" : "=l"(d) : "f"(x)); return d;
}
static __device__ __forceinline__ float2 unpk(ull a){
    float2 f; asm("mov.b64 {%0, %1}, %2;" : "=f"(f.x), "=f"(f.y) : "l"(a)); return f;
}
static __device__ __forceinline__ float softplus_f(float x){
    return fmaxf(x, 0.f) + __logf(1.f + __expf(-fabsf(x)));
}

constexpr int   BN     = 262144;
constexpr int   GROUPS = BN / 4;
constexpr float EPSF   = 1e-12f;

__global__ __launch_bounds__(256)
void hist2d_kernel(const float* __restrict__ wi, const float* __restrict__ cond,
                   const float* __restrict__ w0, const float* __restrict__ b0,
                   const float* __restrict__ w1, const float* __restrict__ b1,
                   const float* __restrict__ w2, const float* __restrict__ b2,
                   const float* __restrict__ w3, const float* __restrict__ b3,
                   float* __restrict__ out)
{
    __shared__ __align__(16) float s_w3[32*256];
    __shared__ __align__(16) float s_b3[256];
    __shared__ float2 s_pair[8][2][32];
    __shared__ __align__(16) float2 s_hb[8][128];   // dup-h during layer3, hist during sampling

    const int tid = threadIdx.x;
    for (int i = tid; i < 32*256; i += 256) s_w3[i] = w3[i];
    if (tid < 256) s_b3[tid] = b3[tid];
    __syncthreads();

    const int lane = tid & 31;
    const int wz   = tid >> 5;
    const int wgid = blockIdx.x * 8 + wz;
    const int nwarp = gridDim.x * 8;

    float2* pA = s_pair[wz][0];
    float2* pB = s_pair[wz][1];
    const ull* pAu = (const ull*)pA;
    const ull* pBu = (const ull*)pB;
    float2* hb2 = s_hb[wz];
    const ull* hbu = (const ull*)hb2;
    float*  hbf = (float*)hb2;

    for (int g = wgid; g < GROUPS; g += nwarp) {
        const int s0 = g << 2;

        // ---- load cond for 4 samples, interleaved by sample pairs ----
        if (lane < 20) {
            int i  = lane % 10;
            int sa = s0 + ((lane >= 10) ? 2 : 0);
            float a = cond[sa*10 + i];
            float b = cond[(sa+1)*10 + i];
            if (lane < 10) pA[i] = make_float2(a, b);
            else           pB[i] = make_float2(a, b);
        }
        __syncwarp();

        // ---- layer 0: 10 -> 32 ----
        ull accA = dup2(__ldg(&b0[lane]));
        ull accB = accA;
        #pragma unroll
        for (int k = 0; k < 10; ++k) {
            ull wk = dup2(__ldg(&w0[k*32 + lane]));
            accA = fma2(pAu[k], wk, accA);
            accB = fma2(pBu[k], wk, accB);
        }
        __syncwarp();
        {
            float2 a = unpk(accA), b = unpk(accB);
            pA[lane] = make_float2(fmaxf(a.x,0.f), fmaxf(a.y,0.f));
            pB[lane] = make_float2(fmaxf(b.x,0.f), fmaxf(b.y,0.f));
        }
        __syncwarp();

        // ---- layer 1: 32 -> 32 ----
        accA = dup2(__ldg(&b1[lane])); accB = accA;
        #pragma unroll
        for (int k = 0; k < 32; ++k) {
            ull wk = dup2(__ldg(&w1[k*32 + lane]));
            accA = fma2(pAu[k], wk, accA);
            accB = fma2(pBu[k], wk, accB);
        }
        __syncwarp();
        {
            float2 a = unpk(accA), b = unpk(accB);
            pA[lane] = make_float2(fmaxf(a.x,0.f), fmaxf(a.y,0.f));
            pB[lane] = make_float2(fmaxf(b.x,0.f), fmaxf(b.y,0.f));
        }
        __syncwarp();

        // ---- layer 2: 32 -> 32, output duplicated (h,h) per sample ----
        accA = dup2(__ldg(&b2[lane])); accB = accA;
        #pragma unroll
        for (int k = 0; k < 32; ++k) {
            ull wk = dup2(__ldg(&w2[k*32 + lane]));
            accA = fma2(pAu[k], wk, accA);
            accB = fma2(pBu[k], wk, accB);
        }
        __syncwarp();
        {
            float2 a = unpk(accA), b = unpk(accB);
            float h0 = fmaxf(a.x,0.f), h1 = fmaxf(a.y,0.f);
            float h2 = fmaxf(b.x,0.f), h3 = fmaxf(b.y,0.f);
            hb2[0*32 + lane] = make_float2(h0, h0);
            hb2[1*32 + lane] = make_float2(h1, h1);
            hb2[2*32 + lane] = make_float2(h2, h2);
            hb2[3*32 + lane] = make_float2(h3, h3);
        }
        __syncwarp();

        // ---- layer 3: 32 -> 256, lane owns cols lane*8 .. lane*8+7 ----
        ull acc[4][4];
        {
            const ulonglong2* bv = (const ulonglong2*)&s_b3[lane*8];
            ulonglong2 b01 = bv[0], b23 = bv[1];
            #pragma unroll
            for (int s = 0; s < 4; ++s) {
                acc[s][0] = b01.x; acc[s][1] = b01.y;
                acc[s][2] = b23.x; acc[s][3] = b23.y;
            }
        }
        #pragma unroll
        for (int k = 0; k < 32; ++k) {
            ull a0 = hbu[k], a1 = hbu[32+k], a2 = hbu[64+k], a3 = hbu[96+k];
            const ulonglong2* wv = (const ulonglong2*)&s_w3[k*256 + lane*8];
            ulonglong2 wlo = wv[0], whi = wv[1];
            acc[0][0] = fma2(a0, wlo.x, acc[0][0]);
            acc[0][1] = fma2(a0, wlo.y, acc[0][1]);
            acc[0][2] = fma2(a0, whi.x, acc[0][2]);
            acc[0][3] = fma2(a0, whi.y, acc[0][3]);
            acc[1][0] = fma2(a1, wlo.x, acc[1][0]);
            acc[1][1] = fma2(a1, wlo.y, acc[1][1]);
            acc[1][2] = fma2(a1, whi.x, acc[1][2]);
            acc[1][3] = fma2(a1, whi.y, acc[1][3]);
            acc[2][0] = fma2(a2, wlo.x, acc[2][0]);
            acc[2][1] = fma2(a2, wlo.y, acc[2][1]);
            acc[2][2] = fma2(a2, whi.x, acc[2][2]);
            acc[2][3] = fma2(a2, whi.y, acc[2][3]);
            acc[3][0] = fma2(a3, wlo.x, acc[3][0]);
            acc[3][1] = fma2(a3, wlo.y, acc[3][1]);
            acc[3][2] = fma2(a3, whi.x, acc[3][2]);
            acc[3][3] = fma2(a3, whi.y, acc[3][3]);
        }

        // ---- softplus + total sums ----
        float v[4][8];
        float half8[4], tot[4];
        #pragma unroll
        for (int s = 0; s < 4; ++s) {
            #pragma unroll
            for (int p = 0; p < 4; ++p) {
                float2 t = unpk(acc[s][p]);
                v[s][2*p]   = softplus_f(t.x);
                v[s][2*p+1] = softplus_f(t.y);
            }
            float r = ((v[s][0]+v[s][1]) + (v[s][2]+v[s][3]))
                    + ((v[s][4]+v[s][5]) + (v[s][6]+v[s][7]));
            half8[s] = r;
            float t = r;
            #pragma unroll
            for (int o = 16; o > 0; o >>= 1) t += __shfl_xor_sync(FULLM, t, o);
            tot[s] = t;
        }

        // ---- inverse-CDF sampling, one sample at a time ----
        #pragma unroll
        for (int s = 0; s < 4; ++s) {
            float norm = __fdividef(1.f, fmaxf(tot[s], EPSF));
            __syncwarp();
            float4* hb4 = (float4*)hbf;
            hb4[lane*2]   = make_float4(v[s][0]*norm, v[s][1]*norm, v[s][2]*norm, v[s][3]*norm);
            hb4[lane*2+1] = make_float4(v[s][4]*norm, v[s][5]*norm, v[s][6]*norm, v[s][7]*norm);
            __syncwarp();

            // pdf_y: row r lives in lanes 2r (x 0..7) and 2r+1 (x 8..15)
            float rh    = half8[s] * norm;
            float rfull = rh + __shfl_xor_sync(FULLM, rh, 1);
            int   li    = lane & 15;
            float pdfy  = __shfl_sync(FULLM, rfull, li*2);

            float cdf = pdfy;
            #pragma unroll
            for (int d = 1; d < 16; d <<= 1) {
                float t = __shfl_up_sync(FULLM, cdf, d);
                if (lane >= d) cdf += t;
            }

            float u_x = __ldg(&wi[(s0+s)*2]);
            float u_y = __ldg(&wi[(s0+s)*2 + 1]);

            unsigned my = __ballot_sync(FULLM, (lane < 16) && (cdf < u_y));
            int   iy   = min(__popc(my), 15);
            float cdfp = (iy > 0) ? __shfl_sync(FULLM, cdf, iy-1) : 0.f;
            float py   = __shfl_sync(FULLM, pdfy, iy);
            float yv   = ((float)iy + __fdividef(u_y - cdfp, fmaxf(py, EPSF))) * 0.0625f;

            float hv   = hbf[iy*16 + li];
            float pdfx = __fdividef(hv, fmaxf(py, EPSF));
            float cdfx = pdfx;
            #pragma unroll
            for (int d = 1; d < 16; d <<= 1) {
                float t = __shfl_up_sync(FULLM, cdfx, d);
                if (lane >= d) cdfx += t;
            }
            unsigned mx = __ballot_sync(FULLM, (lane < 16) && (cdfx < u_x));
            int   ix    = min(__popc(mx), 15);
            float cdfxp = (ix > 0) ? __shfl_sync(FULLM, cdfx, ix-1) : 0.f;
            float px    = __shfl_sync(FULLM, pdfx, ix);
            float xv    = ((float)ix + __fdividef(u_x - cdfxp, fmaxf(px, EPSF))) * 0.0625f;
            float pout  = __shfl_sync(FULLM, hv, ix) * 64.f;

            if (lane == 0) {
                out[(s0+s)*2]      = xv*2.f - 1.f;
                out[(s0+s)*2 + 1]  = yv*2.f - 1.f;
                out[2*BN + s0 + s] = pout;
            }
        }
        __syncwarp();
    }
}

extern "C" void kernel_launch(void* const* d_in, const int* in_sizes, int n_in,
                              void* d_out, int out_size) {
    const float* wi   = (const float*)d_in[0];
    const float* cond = (const float*)d_in[1];
    const float* w0   = (const float*)d_in[2];
    const float* b0   = (const float*)d_in[3];
    const float* w1   = (const float*)d_in[4];
    const float* b1   = (const float*)d_in[5];
    const float* w2   = (const float*)d_in[6];
    const float* b2   = (const float*)d_in[7];
    const float* w3   = (const float*)d_in[8];
    const float* b3   = (const float*)d_in[9];
    (void)in_sizes; (void)n_in; (void)out_size;
    // 2048 blocks * 8 warps = 16384 warps; 65536 groups -> exactly 4 groups/warp
    hist2d_kernel<<<2048, 256>>>(wi, cond, w0, b0, w1, b1, w2, b2, w3, b3, (float*)d_out);
}

// round 2
// speedup vs baseline: 1.4250x; 1.4250x over previous
#include <cuda_runtime.h>

#define FULLM 0xffffffffu
typedef unsigned long long ull;

static __device__ __forceinline__ ull fma2(ull a, ull b, ull c){
    ull d; asm("fma.rn.f32x2 %0, %1, %2, %3;" : "=l"(d) : "l"(a), "l"(b), "l"(c)); return d;
}
static __device__ __forceinline__ ull dup2(float x){
    ull d; asm("mov.b64 %0, {%1, %1};" : "=l"(d) : "f"(x)); return d;
}
static __device__ __forceinline__ float2 unpk(ull a){
    float2 f; asm("mov.b64 {%0, %1}, %2;" : "=f"(f.x), "=f"(f.y) : "l"(a)); return f;
}
static __device__ __forceinline__ float softplus_f(float x){
    return fmaxf(x, 0.f) + __logf(1.f + __expf(-fabsf(x)));
}

constexpr int   BN     = 262144;
constexpr int   GROUPS = BN / 32;          // 8192 block-groups of 32 samples
constexpr float EPSF   = 1e-12f;

__global__ __launch_bounds__(128)
void hist2d_kernel(const float* __restrict__ wi, const float* __restrict__ cond,
                   const float* __restrict__ w0, const float* __restrict__ b0,
                   const float* __restrict__ w1, const float* __restrict__ b1,
                   const float* __restrict__ w2, const float* __restrict__ b2,
                   const float* __restrict__ w3, const float* __restrict__ b3,
                   float* __restrict__ out)
{
    // Per block: 4 warps x 8 samples = 32 samples per group iteration.
    __shared__ __align__(16) float2 s_pair[4][4][32];   // layers 0-2 activations (pair-packed), per warp
    __shared__ __align__(16) float2 s_h[16][32];        // h after layer 2, [pair][k], pair-packed
    __shared__ float s_rows[32][17];                    // unnormalized row sums per sample
    __shared__ float s_hist[32][274];                   // unnormalized hist per sample (256 + pad)

    const int tid  = threadIdx.x;
    const int lane = tid & 31;
    const int w    = tid >> 5;
    const int ci   = w * 32 + lane;        // float2 column index (owns cols 2ci, 2ci+1)
    const int c0   = ci * 2;
    const int rowg = w * 4 + (lane >> 3);  // hist row this lane's cols belong to

    const float2* __restrict__ w3v = (const float2*)w3;
    const float2  b3v = __ldg(&((const float2*)b3)[ci]);

    for (int g = blockIdx.x; g < GROUPS; g += gridDim.x) {
        const int Sblk = g * 32;

        // ================= Phase A: layers 0-2 for this warp's 8 samples =================
        const int S0 = Sblk + w * 8;
        #pragma unroll
        for (int p2 = 0; p2 < 2; ++p2) {
            if (lane < 20) {
                int pl = p2 * 2 + (lane >= 10);
                int i  = lane % 10;
                int sb = S0 + pl * 2;
                s_pair[w][pl][i] = make_float2(__ldg(&cond[sb*10 + i]), __ldg(&cond[sb*10 + 10 + i]));
            }
        }
        __syncwarp();

        ull acc[4];

        // ---- layer 0: 10 -> 32 ----
        {
            ull b = dup2(__ldg(&b0[lane]));
            #pragma unroll
            for (int p = 0; p < 4; ++p) acc[p] = b;
            #pragma unroll
            for (int k = 0; k < 10; k += 2) {
                ull wkA = dup2(__ldg(&w0[k*32 + lane]));
                ull wkB = dup2(__ldg(&w0[(k+1)*32 + lane]));
                #pragma unroll
                for (int p = 0; p < 4; ++p) {
                    ulonglong2 h2 = *(const ulonglong2*)&s_pair[w][p][k];
                    acc[p] = fma2(h2.x, wkA, acc[p]);
                    acc[p] = fma2(h2.y, wkB, acc[p]);
                }
            }
            __syncwarp();
            #pragma unroll
            for (int p = 0; p < 4; ++p) {
                float2 f = unpk(acc[p]);
                s_pair[w][p][lane] = make_float2(fmaxf(f.x, 0.f), fmaxf(f.y, 0.f));
            }
            __syncwarp();
        }

        // ---- layer 1: 32 -> 32 ----
        {
            ull b = dup2(__ldg(&b1[lane]));
            #pragma unroll
            for (int p = 0; p < 4; ++p) acc[p] = b;
            #pragma unroll 8
            for (int k = 0; k < 32; k += 2) {
                ull wkA = dup2(__ldg(&w1[k*32 + lane]));
                ull wkB = dup2(__ldg(&w1[(k+1)*32 + lane]));
                #pragma unroll
                for (int p = 0; p < 4; ++p) {
                    ulonglong2 h2 = *(const ulonglong2*)&s_pair[w][p][k];
                    acc[p] = fma2(h2.x, wkA, acc[p]);
                    acc[p] = fma2(h2.y, wkB, acc[p]);
                }
            }
            __syncwarp();
            #pragma unroll
            for (int p = 0; p < 4; ++p) {
                float2 f = unpk(acc[p]);
                s_pair[w][p][lane] = make_float2(fmaxf(f.x, 0.f), fmaxf(f.y, 0.f));
            }
            __syncwarp();
        }

        // ---- layer 2: 32 -> 32, publish to block-shared s_h ----
        {
            ull b = dup2(__ldg(&b2[lane]));
            #pragma unroll
            for (int p = 0; p < 4; ++p) acc[p] = b;
            #pragma unroll 8
            for (int k = 0; k < 32; k += 2) {
                ull wkA = dup2(__ldg(&w2[k*32 + lane]));
                ull wkB = dup2(__ldg(&w2[(k+1)*32 + lane]));
                #pragma unroll
                for (int p = 0; p < 4; ++p) {
                    ulonglong2 h2 = *(const ulonglong2*)&s_pair[w][p][k];
                    acc[p] = fma2(h2.x, wkA, acc[p]);
                    acc[p] = fma2(h2.y, wkB, acc[p]);
                }
            }
            __syncwarp();
            #pragma unroll
            for (int p = 0; p < 4; ++p) {
                float2 f = unpk(acc[p]);
                s_h[w*4 + p][lane] = make_float2(fmaxf(f.x, 0.f), fmaxf(f.y, 0.f));
            }
        }
        __syncthreads();

        // ================= Phase B: layer 3 (32 -> 256), all 16 pairs, this warp's 2 cols =================
        ull acc3[16][2];
        {
            ull bd0 = dup2(b3v.x), bd1 = dup2(b3v.y);
            #pragma unroll
            for (int p = 0; p < 16; ++p) { acc3[p][0] = bd0; acc3[p][1] = bd1; }
        }
        #pragma unroll 4
        for (int k = 0; k < 32; k += 2) {
            float2 wA = __ldg(&w3v[k*128 + ci]);
            float2 wB = __ldg(&w3v[(k+1)*128 + ci]);
            ull wA0 = dup2(wA.x), wA1 = dup2(wA.y);
            ull wB0 = dup2(wB.x), wB1 = dup2(wB.y);
            #pragma unroll
            for (int p = 0; p < 16; ++p) {
                ulonglong2 h2 = *(const ulonglong2*)&s_h[p][k];
                acc3[p][0] = fma2(h2.x, wA0, acc3[p][0]);
                acc3[p][1] = fma2(h2.x, wA1, acc3[p][1]);
                acc3[p][0] = fma2(h2.y, wB0, acc3[p][0]);
                acc3[p][1] = fma2(h2.y, wB1, acc3[p][1]);
            }
        }

        // softplus, hist write, register row-sum reduction (8-lane butterflies)
        #pragma unroll
        for (int p = 0; p < 16; ++p) {
            float2 f0 = unpk(acc3[p][0]);   // (sampleA, sampleB) for col c0
            float2 f1 = unpk(acc3[p][1]);   // (sampleA, sampleB) for col c0+1
            float sa0 = softplus_f(f0.x), sb0 = softplus_f(f0.y);
            float sa1 = softplus_f(f1.x), sb1 = softplus_f(f1.y);
            *(float2*)&s_hist[2*p    ][c0] = make_float2(sa0, sa1);
            *(float2*)&s_hist[2*p + 1][c0] = make_float2(sb0, sb1);
            float rx = sa0 + sa1;
            float ry = sb0 + sb1;
            #pragma unroll
            for (int o = 1; o < 8; o <<= 1) {
                rx += __shfl_xor_sync(FULLM, rx, o);
                ry += __shfl_xor_sync(FULLM, ry, o);
            }
            if ((lane & 7) == 0) {
                s_rows[2*p    ][rowg] = rx;
                s_rows[2*p + 1][rowg] = ry;
            }
        }
        __syncthreads();

        // ================= Phase C: inverse-CDF sampling, 2 samples per warp at a time =================
        const int li = lane & 15;
        #pragma unroll
        for (int j = 0; j < 4; ++j) {
            const int sa   = w * 8 + 2 * j;
            const int samp = (lane < 16) ? sa : (sa + 1);
            const int S    = Sblk + samp;

            float rowsum = s_rows[samp][li];
            float tot = rowsum;
            #pragma unroll
            for (int o = 1; o < 16; o <<= 1) tot += __shfl_xor_sync(FULLM, tot, o);
            float norm = __fdividef(1.f, fmaxf(tot, EPSF));
            float pdfy = rowsum * norm;

            float cdf = pdfy;
            #pragma unroll
            for (int d = 1; d < 16; d <<= 1) {
                float t = __shfl_up_sync(FULLM, cdf, d, 16);
                if (li >= d) cdf += t;
            }

            float u_x = __ldg(&wi[S*2]);
            float u_y = __ldg(&wi[S*2 + 1]);

            unsigned bal = __ballot_sync(FULLM, cdf < u_y);
            unsigned mym = (lane < 16) ? (bal & 0xFFFFu) : (bal >> 16);
            int   iy   = min(__popc(mym), 15);
            float cdfp = __shfl_sync(FULLM, cdf, max(iy - 1, 0), 16);
            cdfp = (iy > 0) ? cdfp : 0.f;
            float py   = __shfl_sync(FULLM, pdfy, iy, 16);
            float yv   = ((float)iy + __fdividef(u_y - cdfp, fmaxf(py, EPSF))) * 0.0625f;

            float hvn  = s_hist[samp][iy*16 + li] * norm;
            float pdfx = __fdividef(hvn, fmaxf(py, EPSF));
            float cdfx = pdfx;
            #pragma unroll
            for (int d = 1; d < 16; d <<= 1) {
                float t = __shfl_up_sync(FULLM, cdfx, d, 16);
                if (li >= d) cdfx += t;
            }
            unsigned balx = __ballot_sync(FULLM, cdfx < u_x);
            unsigned mymx = (lane < 16) ? (balx & 0xFFFFu) : (balx >> 16);
            int   ix    = min(__popc(mymx), 15);
            float cdfxp = __shfl_sync(FULLM, cdfx, max(ix - 1, 0), 16);
            cdfxp = (ix > 0) ? cdfxp : 0.f;
            float px    = __shfl_sync(FULLM, pdfx, ix, 16);
            float xv    = ((float)ix + __fdividef(u_x - cdfxp, fmaxf(px, EPSF))) * 0.0625f;
            float pout  = __shfl_sync(FULLM, hvn, ix, 16) * 64.f;

            if (li == 0) {
                out[S*2]       = xv * 2.f - 1.f;
                out[S*2 + 1]   = yv * 2.f - 1.f;
                out[2*BN + S]  = pout;
            }
        }
        __syncthreads();
    }
}

extern "C" void kernel_launch(void* const* d_in, const int* in_sizes, int n_in,
                              void* d_out, int out_size) {
    const float* wi   = (const float*)d_in[0];
    const float* cond = (const float*)d_in[1];
    const float* w0   = (const float*)d_in[2];
    const float* b0   = (const float*)d_in[3];
    const float* w1   = (const float*)d_in[4];
    const float* b1   = (const float*)d_in[5];
    const float* w2   = (const float*)d_in[6];
    const float* b2   = (const float*)d_in[7];
    const float* w3   = (const float*)d_in[8];
    const float* b3   = (const float*)d_in[9];
    (void)in_sizes; (void)n_in; (void)out_size;
    hist2d_kernel<<<2048, 128>>>(wi, cond, w0, b0, w1, b1, w2, b2, w3, b3, (float*)d_out);
}